// round 14
// baseline (speedup 1.0000x reference)
#include <cuda_runtime.h>

// Round 14: R9 (block-per-segment, T=128, 4-deep float4 batches, no max pass,
// __stcs stores) + REGISTER CARRY: the first 4-deep batch (2048 elems, i.e.
// the ENTIRE segment for ~63% of blocks) stays live in registers across the
// block reduce, so pass 2 for that portion is store-only — no re-read on the
// post-barrier critical path. Overflow re-reads from L1 as before.

#define T 128
#define NW (T / 32)

__global__ void __launch_bounds__(T)
jagged_log_softmax_kernel(const float* __restrict__ logits,
                          const int* __restrict__ prefix_sum,
                          float* __restrict__ out) {
    __shared__ float sm[NW];
    __shared__ float s_lse;

    const int seg   = blockIdx.x;
    const int start = (seg == 0) ? 0 : __ldg(&prefix_sum[seg - 1]);
    const int end   = __ldg(&prefix_sum[seg]);
    if (start >= end) return;

    const int tid  = threadIdx.x;
    const int lane = tid & 31;
    const int warp = tid >> 5;

    // head [start,astart), float4 body [astart,aend), tail [aend,end)
    int astart = (start + 3) & ~3; if (astart > end) astart = end;
    int aend   = end & ~3;         if (aend < astart) aend = astart;

    const float4* __restrict__ logits4 = (const float4*)logits;
    const int STEP = T * 4;

    // held region: first 4 batches (up to 2048 elems)
    const int held_end = min(aend, astart + 4 * STEP);

    // per-thread held indices
    const int h0 = astart + tid * 4;
    const int h1 = h0 + STEP;
    const int h2 = h0 + 2 * STEP;
    const int h3 = h0 + 3 * STEP;

    float4 v0, v1, v2, v3;
    const bool b0 = (h0 < held_end);
    const bool b1 = (h1 < held_end);
    const bool b2 = (h2 < held_end);
    const bool b3 = (h3 < held_end);

    // ---- Pass 1: sum of exp(x) ----
    float s = 0.0f;

    for (int i = start + tid; i < astart; i += T)
        s += __expf(__ldg(&logits[i]));

    if (b0) v0 = __ldg(&logits4[h0 >> 2]);
    if (b1) v1 = __ldg(&logits4[h1 >> 2]);
    if (b2) v2 = __ldg(&logits4[h2 >> 2]);
    if (b3) v3 = __ldg(&logits4[h3 >> 2]);
    if (b0) s += __expf(v0.x) + __expf(v0.y) + __expf(v0.z) + __expf(v0.w);
    if (b1) s += __expf(v1.x) + __expf(v1.y) + __expf(v1.z) + __expf(v1.w);
    if (b2) s += __expf(v2.x) + __expf(v2.y) + __expf(v2.z) + __expf(v2.w);
    if (b3) s += __expf(v3.x) + __expf(v3.y) + __expf(v3.z) + __expf(v3.w);

    // overflow body (beyond held region), 4-deep batched
    int i = held_end + tid * 4;
    for (; i + 3 * STEP < aend; i += 4 * STEP) {
        float4 w0 = __ldg(&logits4[(i           ) >> 2]);
        float4 w1 = __ldg(&logits4[(i +     STEP) >> 2]);
        float4 w2 = __ldg(&logits4[(i + 2 * STEP) >> 2]);
        float4 w3 = __ldg(&logits4[(i + 3 * STEP) >> 2]);
        s += __expf(w0.x) + __expf(w0.y) + __expf(w0.z) + __expf(w0.w);
        s += __expf(w1.x) + __expf(w1.y) + __expf(w1.z) + __expf(w1.w);
        s += __expf(w2.x) + __expf(w2.y) + __expf(w2.z) + __expf(w2.w);
        s += __expf(w3.x) + __expf(w3.y) + __expf(w3.z) + __expf(w3.w);
    }
    for (; i < aend; i += STEP) {
        float4 w = __ldg(&logits4[i >> 2]);
        s += __expf(w.x) + __expf(w.y) + __expf(w.z) + __expf(w.w);
    }
    for (int j = aend + tid; j < end; j += T)
        s += __expf(__ldg(&logits[j]));

    // ---- block reduce (4 warps) ----
    #pragma unroll
    for (int o = 16; o > 0; o >>= 1)
        s += __shfl_xor_sync(0xFFFFFFFFu, s, o);
    if (lane == 0) sm[warp] = s;
    __syncthreads();
    if (warp == 0) {
        float v = (lane < NW) ? sm[lane] : 0.0f;
        #pragma unroll
        for (int o = NW / 2; o > 0; o >>= 1)
            v += __shfl_xor_sync(0xFFFFFFFFu, v, o);
        if (lane == 0) s_lse = __logf(v);
    }
    __syncthreads();
    const float lse = s_lse;

    // ---- Pass 2: held part stores straight from registers ----
    if (b0) {
        float4 r; r.x = v0.x - lse; r.y = v0.y - lse; r.z = v0.z - lse; r.w = v0.w - lse;
        __stcs((float4*)&out[h0], r);
    }
    if (b1) {
        float4 r; r.x = v1.x - lse; r.y = v1.y - lse; r.z = v1.z - lse; r.w = v1.w - lse;
        __stcs((float4*)&out[h1], r);
    }
    if (b2) {
        float4 r; r.x = v2.x - lse; r.y = v2.y - lse; r.z = v2.z - lse; r.w = v2.w - lse;
        __stcs((float4*)&out[h2], r);
    }
    if (b3) {
        float4 r; r.x = v3.x - lse; r.y = v3.y - lse; r.z = v3.z - lse; r.w = v3.w - lse;
        __stcs((float4*)&out[h3], r);
    }

    // head/tail scalars
    for (int j = start + tid; j < astart; j += T)
        __stcs(&out[j], __ldg(&logits[j]) - lse);
    for (int j = aend + tid; j < end; j += T)
        __stcs(&out[j], __ldg(&logits[j]) - lse);

    // overflow body: re-read (L1 hit) + write
    i = held_end + tid * 4;
    for (; i + 3 * STEP < aend; i += 4 * STEP) {
        float4 w0 = __ldg(&logits4[(i           ) >> 2]);
        float4 w1 = __ldg(&logits4[(i +     STEP) >> 2]);
        float4 w2 = __ldg(&logits4[(i + 2 * STEP) >> 2]);
        float4 w3 = __ldg(&logits4[(i + 3 * STEP) >> 2]);
        float4 r0, r1, r2, r3;
        r0.x = w0.x - lse; r0.y = w0.y - lse; r0.z = w0.z - lse; r0.w = w0.w - lse;
        r1.x = w1.x - lse; r1.y = w1.y - lse; r1.z = w1.z - lse; r1.w = w1.w - lse;
        r2.x = w2.x - lse; r2.y = w2.y - lse; r2.z = w2.z - lse; r2.w = w2.w - lse;
        r3.x = w3.x - lse; r3.y = w3.y - lse; r3.z = w3.z - lse; r3.w = w3.w - lse;
        __stcs((float4*)&out[i           ], r0);
        __stcs((float4*)&out[i +     STEP], r1);
        __stcs((float4*)&out[i + 2 * STEP], r2);
        __stcs((float4*)&out[i + 3 * STEP], r3);
    }
    for (; i < aend; i += STEP) {
        float4 w = __ldg(&logits4[i >> 2]);
        float4 r;
        r.x = w.x - lse; r.y = w.y - lse; r.z = w.z - lse; r.w = w.w - lse;
        __stcs((float4*)&out[i], r);
    }
}

extern "C" void kernel_launch(void* const* d_in, const int* in_sizes, int n_in,
                              void* d_out, int out_size) {
    const float* logits     = (const float*)d_in[0];
    const int*   prefix_sum = (const int*)d_in[1];
    float*       out        = (float*)d_out;

    const int num_segs = in_sizes[1];
    jagged_log_softmax_kernel<<<num_segs, T>>>(logits, prefix_sum, out);
}

// round 15
// speedup vs baseline: 1.2276x; 1.2276x over previous
#include <cuda_runtime.h>

// Round 15: R9 + TWO segments per block (A = bid, B = bid + gridDim.x).
// Amortizes the reduce/barrier phase over 2x data: pass1(A); pass1(B);
// ONE joint block reduce (both sums, interleaved shuffles, 1 bar round);
// pass2(A); pass2(B). Bodies identical to R9 (4-deep float4 batches,
// no max pass, __stcs streaming stores, pass-2 L1 re-read).

#define T 128
#define NW (T / 32)

__device__ __forceinline__ float sum_exp_range(const float* __restrict__ logits,
                                               int start, int end, int tid) {
    int astart = (start + 3) & ~3; if (astart > end) astart = end;
    int aend   = end & ~3;         if (aend < astart) aend = astart;

    const float4* __restrict__ logits4 = (const float4*)logits;
    const int STEP = T * 4;

    float s = 0.0f;
    for (int i = start + tid; i < astart; i += T)
        s += __expf(__ldg(&logits[i]));

    int i = astart + tid * 4;
    for (; i + 3 * STEP < aend; i += 4 * STEP) {
        float4 v0 = __ldg(&logits4[(i           ) >> 2]);
        float4 v1 = __ldg(&logits4[(i +     STEP) >> 2]);
        float4 v2 = __ldg(&logits4[(i + 2 * STEP) >> 2]);
        float4 v3 = __ldg(&logits4[(i + 3 * STEP) >> 2]);
        s += __expf(v0.x) + __expf(v0.y) + __expf(v0.z) + __expf(v0.w);
        s += __expf(v1.x) + __expf(v1.y) + __expf(v1.z) + __expf(v1.w);
        s += __expf(v2.x) + __expf(v2.y) + __expf(v2.z) + __expf(v2.w);
        s += __expf(v3.x) + __expf(v3.y) + __expf(v3.z) + __expf(v3.w);
    }
    for (; i < aend; i += STEP) {
        float4 v = __ldg(&logits4[i >> 2]);
        s += __expf(v.x) + __expf(v.y) + __expf(v.z) + __expf(v.w);
    }
    for (int j = aend + tid; j < end; j += T)
        s += __expf(__ldg(&logits[j]));
    return s;
}

__device__ __forceinline__ void write_range(const float* __restrict__ logits,
                                            float* __restrict__ out,
                                            int start, int end, int tid, float lse) {
    int astart = (start + 3) & ~3; if (astart > end) astart = end;
    int aend   = end & ~3;         if (aend < astart) aend = astart;

    const float4* __restrict__ logits4 = (const float4*)logits;
    const int STEP = T * 4;

    for (int j = start + tid; j < astart; j += T)
        __stcs(&out[j], __ldg(&logits[j]) - lse);

    int i = astart + tid * 4;
    for (; i + 3 * STEP < aend; i += 4 * STEP) {
        float4 v0 = __ldg(&logits4[(i           ) >> 2]);
        float4 v1 = __ldg(&logits4[(i +     STEP) >> 2]);
        float4 v2 = __ldg(&logits4[(i + 2 * STEP) >> 2]);
        float4 v3 = __ldg(&logits4[(i + 3 * STEP) >> 2]);
        float4 r0, r1, r2, r3;
        r0.x = v0.x - lse; r0.y = v0.y - lse; r0.z = v0.z - lse; r0.w = v0.w - lse;
        r1.x = v1.x - lse; r1.y = v1.y - lse; r1.z = v1.z - lse; r1.w = v1.w - lse;
        r2.x = v2.x - lse; r2.y = v2.y - lse; r2.z = v2.z - lse; r2.w = v2.w - lse;
        r3.x = v3.x - lse; r3.y = v3.y - lse; r3.z = v3.z - lse; r3.w = v3.w - lse;
        __stcs((float4*)&out[i           ], r0);
        __stcs((float4*)&out[i +     STEP], r1);
        __stcs((float4*)&out[i + 2 * STEP], r2);
        __stcs((float4*)&out[i + 3 * STEP], r3);
    }
    for (; i < aend; i += STEP) {
        float4 v = __ldg(&logits4[i >> 2]);
        float4 r;
        r.x = v.x - lse; r.y = v.y - lse; r.z = v.z - lse; r.w = v.w - lse;
        __stcs((float4*)&out[i], r);
    }
    for (int j = aend + tid; j < end; j += T)
        __stcs(&out[j], __ldg(&logits[j]) - lse);
}

__global__ void __launch_bounds__(T)
jagged_log_softmax_kernel(const float* __restrict__ logits,
                          const int* __restrict__ prefix_sum,
                          float* __restrict__ out,
                          int nseg) {
    __shared__ float sm[2][NW];
    __shared__ float s_lse[2];

    const int tid  = threadIdx.x;
    const int lane = tid & 31;
    const int warp = tid >> 5;

    const int segA = blockIdx.x;
    const int segB = blockIdx.x + gridDim.x;

    const int startA = (segA == 0) ? 0 : __ldg(&prefix_sum[segA - 1]);
    const int endA   = __ldg(&prefix_sum[segA]);
    const bool hasB  = (segB < nseg);
    const int startB = hasB ? __ldg(&prefix_sum[segB - 1]) : 0;   // segB >= 1 always
    const int endB   = hasB ? __ldg(&prefix_sum[segB]) : 0;

    const bool doA = (startA < endA);
    const bool doB = hasB && (startB < endB);

    // ---- pass 1 for both segments (back-to-back memory bursts) ----
    float sa = doA ? sum_exp_range(logits, startA, endA, tid) : 0.0f;
    float sb = doB ? sum_exp_range(logits, startB, endB, tid) : 0.0f;

    // ---- joint block reduce: interleaved shuffle chains, one bar round ----
    #pragma unroll
    for (int o = 16; o > 0; o >>= 1) {
        sa += __shfl_xor_sync(0xFFFFFFFFu, sa, o);
        sb += __shfl_xor_sync(0xFFFFFFFFu, sb, o);
    }
    if (lane == 0) { sm[0][warp] = sa; sm[1][warp] = sb; }
    __syncthreads();
    if (warp == 0) {
        float v = (lane < NW) ? sm[0][lane] : 0.0f;
        #pragma unroll
        for (int o = NW / 2; o > 0; o >>= 1)
            v += __shfl_xor_sync(0xFFFFFFFFu, v, o);
        if (lane == 0) s_lse[0] = __logf(v);
    } else if (warp == 1) {
        float v = (lane < NW) ? sm[1][lane] : 0.0f;
        #pragma unroll
        for (int o = NW / 2; o > 0; o >>= 1)
            v += __shfl_xor_sync(0xFFFFFFFFu, v, o);
        if (lane == 0) s_lse[1] = __logf(v);
    }
    __syncthreads();

    // ---- pass 2 for both segments ----
    if (doA) write_range(logits, out, startA, endA, tid, s_lse[0]);
    if (doB) write_range(logits, out, startB, endB, tid, s_lse[1]);
}

extern "C" void kernel_launch(void* const* d_in, const int* in_sizes, int n_in,
                              void* d_out, int out_size) {
    const float* logits     = (const float*)d_in[0];
    const int*   prefix_sum = (const int*)d_in[1];
    float*       out        = (float*)d_out;

    const int num_segs = in_sizes[1];
    const int grid     = (num_segs + 1) / 2;
    jagged_log_softmax_kernel<<<grid, T>>>(logits, prefix_sum, out, num_segs);
}